// round 10
// baseline (speedup 1.0000x reference)
#include <cuda_runtime.h>
#include <math.h>

#define TS 32
#define NT 256
#define IN_DIM 40    // TS + 2*4 halo
#define IN_STR 44    // padded stride (16B-aligned rows for float4 stage-A stores)
#define TMP_W 36
#define TMP_STR 37
#define BLUR_DIM 36
#define BLUR_STR 37
#define GM_DIM 34
#define GM_STR 35

// channel-block strides
#define IN_CH   (IN_DIM * IN_STR)     // 1760
#define TMP_CH  (IN_DIM * TMP_STR)    // 1480
#define BLUR_CH (BLUR_DIM * BLUR_STR) // 1332

#define S_IN(c, r, x)   s_pool[(c) * IN_CH + (r) * IN_STR + (x)]
#define S_TMP(c, r, x)  s_tmpa[(c) * TMP_CH + (r) * TMP_STR + (x)]
#define S_BLUR(c, r, x) s_pool[(c) * BLUR_CH + (r) * BLUR_STR + (x)]

__global__ __launch_bounds__(NT) void canny_fused_kernel(
    const float* __restrict__ img, float* __restrict__ out,
    int H, int W)
{
    __shared__ float s_pool[3 * IN_CH];     // s_in aliased by s_blur (blur: 3*1332 <= 3*1760)
    __shared__ float s_tmpa[3 * TMP_CH];
    __shared__ float s_gmag[GM_DIM * GM_STR];
    __shared__ int s_noff[8];

    const int tid = threadIdx.x;
    const int x0 = blockIdx.x * TS;
    const int y0 = blockIdx.y * TS;
    const int b  = blockIdx.z;

    // R1 literals, verbatim
    const float G0 = 0.13533528f;   // exp(-2)
    const float G1 = 0.60653067f;   // exp(-0.5)

    if (tid < 8) {
        const int ddy[8] = {0, 1, 1, 1, 0, -1, -1, -1};
        const int ddx[8] = {1, 1, 0, -1, -1, -1, 0, 1};
        s_noff[tid] = ddy[tid] * GM_STR + ddx[tid];
    }

    // stage D mapping: 238 threads, one column x 5-tall segment, channels looped inside
    const int tD_ty = tid / GM_DIM, tD_c = tid - tD_ty * GM_DIM; // ty 0..6(7), col 0..33
    const int r0   = tD_ty * 5;
    const int rend = (r0 + 5 < GM_DIM) ? (r0 + 5) : GM_DIM;

    const bool interior = (x0 >= 32) && (x0 <= 448) && (y0 >= 32) && (y0 <= 448);
    const float* base = img + ((size_t)b * 3) * H * W;
    const size_t HW = (size_t)H * W;

    // per-thread channel accumulators
    float amag[5], agx[5], agy[5];

    // ---- stage A: load all 3 channels' 40x40 tiles ----
    if (interior) {
        for (int u = tid; u < 1200; u += NT) {          // 3 ch x 40 rows x 10 float4
            int c = u / 400, rem = u - c * 400;
            int r = rem / 10, q = rem - r * 10;
            float4 v = *(const float4*)(base + (size_t)c * HW + (size_t)(y0 - 4 + r) * W + (x0 - 4) + 4 * q);
            *(float4*)(&S_IN(c, r, 4 * q)) = v;
        }
    } else {
        for (int u = tid; u < 4800; u += NT) {          // 3 ch x 40 x 40 scalar, guarded
            int c = u / 1600, rem = u - c * 1600;
            int r = rem / 40, x = rem - r * 40;
            int gy = y0 - 4 + r, gx = x0 - 4 + x;
            float v = 0.0f;
            if (gy >= 0 && gy < H && gx >= 0 && gx < W) v = base[(size_t)c * HW + (size_t)gy * W + gx];
            S_IN(c, r, x) = v;
        }
    }
    __syncthreads();

    // ---- stage B: horizontal gaussian, rolling 5-tap window, all channels ----
    // pinned contraction (A): fma(G0, w0+w4, fmul(G1, w1+w3)) + w2
    for (int u = tid; u < 720; u += NT) {               // 3 ch x 40 rows x 6 segments
        int c = u / 240, rem = u - c * 240;
        int r = rem / 6, c0 = (rem - r * 6) * 6;
        float w0 = S_IN(c, r, c0),     w1 = S_IN(c, r, c0 + 1), w2 = S_IN(c, r, c0 + 2);
        float w3 = S_IN(c, r, c0 + 3), w4 = S_IN(c, r, c0 + 4);
        #pragma unroll
        for (int j = 0; j < 6; ++j) {
            int cc = c0 + j;
            float f1 = __fadd_rn(w0, w4);
            float f2 = __fadd_rn(w1, w3);
            S_TMP(c, r, cc) = __fadd_rn(__fmaf_rn(G0, f1, __fmul_rn(G1, f2)), w2);
            if (j < 5) {
                float wn = S_IN(c, r, cc + 5);
                w0 = w1; w1 = w2; w2 = w3; w3 = w4; w4 = wn;
            }
        }
    }
    __syncthreads();

    // ---- stage C: vertical gaussian, rolling window down y; 0 outside image ----
    // (writes s_blur, aliasing s_in — s_in fully consumed by stage B)
    for (int u = tid; u < 648; u += NT) {               // 3 ch x 6 row-segs x 36 cols
        int c = u / 216, rem = u - c * 216;
        int rs = rem / 36, cc = rem - rs * 36;
        int rr0 = rs * 6;
        float w0 = S_TMP(c, rr0, cc),     w1 = S_TMP(c, rr0 + 1, cc), w2 = S_TMP(c, rr0 + 2, cc);
        float w3 = S_TMP(c, rr0 + 3, cc), w4 = S_TMP(c, rr0 + 4, cc);
        #pragma unroll
        for (int j = 0; j < 6; ++j) {
            int r = rr0 + j;
            int gy = y0 - 2 + r, gx = x0 - 2 + cc;
            float v = 0.0f;
            if (gy >= 0 && gy < H && gx >= 0 && gx < W) {
                float f1 = __fadd_rn(w0, w4);
                float f2 = __fadd_rn(w1, w3);
                v = __fadd_rn(__fmaf_rn(G0, f1, __fmul_rn(G1, f2)), w2);
            }
            S_BLUR(c, r, cc) = v;
            if (j < 5) {
                float wn = S_TMP(c, r + 5, cc);
                w0 = w1; w1 = w2; w2 = w3; w3 = w4; w4 = wn;
            }
        }
    }
    __syncthreads();

    // ---- stage D: sobel + grad magnitude, rolling 3x3 window, channels inner ----
    // pinned forms proven value-identical (R5 == R8 fingerprint)
    if (tid < 238) {
        int cc = tD_c;
        for (int c = 0; c < 3; ++c) {
            float t0 = S_BLUR(c, r0, cc),     t1 = S_BLUR(c, r0, cc + 1),     t2 = S_BLUR(c, r0, cc + 2);
            float m0 = S_BLUR(c, r0 + 1, cc), m1 = S_BLUR(c, r0 + 1, cc + 1), m2 = S_BLUR(c, r0 + 1, cc + 2);
            #pragma unroll
            for (int k = 0; k < 5; ++k) {
                int r = r0 + k;
                if (r < rend) {
                    float b0 = S_BLUR(c, r + 2, cc), b1 = S_BLUR(c, r + 2, cc + 1), b2 = S_BLUR(c, r + 2, cc + 2);
                    int gyp = y0 - 1 + r, gxp = x0 - 1 + cc;
                    float mag = 0.0f, gxv = 0.0f, gyv = 0.0f;
                    if (gyp >= 0 && gyp < H && gxp >= 0 && gxp < W) {
                        float d1 = __fadd_rn(t0, -t2);
                        float d2 = __fadd_rn(m0, -m2);
                        float d3 = __fadd_rn(b0, -b2);
                        gxv = __fadd_rn(__fmaf_rn(2.0f, d2, d1), d3);
                        float ta = __fadd_rn(__fmaf_rn(2.0f, t1, t0), t2);
                        float tb = __fadd_rn(__fmaf_rn(2.0f, b1, b0), b2);
                        gyv = __fadd_rn(ta, -tb);
                        mag = sqrtf(__fmaf_rn(gxv, gxv, __fmul_rn(gyv, gyv)));
                    }
                    if (c == 0) { amag[k] = mag;  agx[k] = gxv;  agy[k] = gyv; }
                    else {
                        amag[k] = __fadd_rn(amag[k], mag);
                        agx[k]  = __fadd_rn(agx[k], gxv);
                        agy[k]  = __fadd_rn(agy[k], gyv);
                    }
                    t0 = m0; t1 = m1; t2 = m2;
                    m0 = b0; m1 = b1; m2 = b2;
                }
            }
        }
        // write summed grad-mag for neighbor gathers
        #pragma unroll
        for (int k = 0; k < 5; ++k) {
            int r = r0 + k;
            if (r < rend) s_gmag[r * GM_STR + cc] = amag[k];
        }
    }
    __syncthreads();

    // ---- orientation quantization + directional NMS + threshold (pinned) ----
    const float RAD2DEG = 180.0f / 3.14159f;  // matches reference literal
    if (tid < 238) {
        int cc = tD_c;
        #pragma unroll
        for (int k = 0; k < 5; ++k) {
            int r = r0 + k;
            if (r < rend && r >= 1 && r <= TS && cc >= 1 && cc <= TS) {
                float gm = amag[k];
                float ang = __fmaf_rn(atan2f(agy[k], agx[k]), RAD2DEG, 180.0f);
                int q = (int)rintf(__fdiv_rn(ang, 45.0f));   // 0..8, half-to-even like jnp.round
                int ip = q & 7;
                int in_ = (q + 4) & 7;
                int ci = r * GM_STR + cc;
                float pos = __fadd_rn(gm, -s_gmag[ci + s_noff[ip]]);
                float neg = __fadd_rn(gm, -s_gmag[ci + s_noff[in_]]);
                float thin = (fminf(pos, neg) > 0.0f) ? gm : 0.0f;
                float res = (thin < 10.0f) ? 0.0f : thin;
                out[((size_t)b * H + (y0 + r - 1)) * W + (x0 + cc - 1)] = res;
            }
        }
    }
}

extern "C" void kernel_launch(void* const* d_in, const int* in_sizes, int n_in,
                              void* d_out, int out_size)
{
    const float* img = (const float*)d_in[0];
    float* out = (float*)d_out;
    const int H = 512, W = 512;
    int B = in_sizes[0] / (3 * H * W);   // 16
    dim3 grid(W / TS, H / TS, B);
    canny_fused_kernel<<<grid, NT>>>(img, out, H, W);
}